// round 3
// baseline (speedup 1.0000x reference)
#include <cuda_runtime.h>
#include <math.h>

// Problem constants (fixed by dataset)
#define TT 1600
#define NN 32
#define CC 512
#define SS 200
#define LL (2 * SS + 1)          // 401
#define NWC 13                   // compute warps (13*32 = 416 >= 401)
#define RING 32                  // row ring slots (power of 2)
#define HR 8                     // halo ring slots (power of 2)
#define THREADS ((NWC + 1) * 32) // 448: 13 compute warps + 1 producer warp
#define LOG2E 1.4426950408889634f
#define LN2   0.6931471805599453f
#define NEG2  (-1.0e30f * 1.4426950408889634f)

// Dynamic smem layout (bytes)
#define OFF_ROWS   0                         // float rowbuf[RING][CC]  = 65536
#define OFF_ALPHA  (RING * CC * 4)           // float shAlpha[LL]       (1604 -> pad 1664)
#define OFF_RTAG   (OFF_ALPHA + 1664)        // int rowtag[RING]        (128)
#define OFF_PROG   (OFF_RTAG + 128)          // int prog[16]            (64)
#define OFF_HALO   (OFF_PROG + 64)           // u64 halo[NWC][HR][2]    (1664)
#define SMEM_BYTES (OFF_HALO + 1664)         // ~69 KB

__device__ float g_per_ex[NN];
__device__ unsigned int g_count;

__device__ __forceinline__ float ex2f(float x) {
    float y; asm("ex2.approx.ftz.f32 %0, %1;" : "=f"(y) : "f"(x)); return y;
}
__device__ __forceinline__ float lg2f(float x) {
    float y; asm("lg2.approx.ftz.f32 %0, %1;" : "=f"(y) : "f"(x)); return y;
}
__device__ __forceinline__ void cp_async16(void* smem_dst, const void* gmem_src) {
    unsigned s = (unsigned)__cvta_generic_to_shared(smem_dst);
    asm volatile("cp.async.ca.shared.global [%0], [%1], 16;" :: "r"(s), "l"(gmem_src));
}
__device__ __forceinline__ void cp_commit() { asm volatile("cp.async.commit_group;"); }
template<int N>
__device__ __forceinline__ void cp_wait() { asm volatile("cp.async.wait_group %0;" :: "n"(N)); }

__global__ void __launch_bounds__(THREADS, 1)
ctc_fused_kernel(const float* __restrict__ lp,       // (T, N, C)
                 const int*   __restrict__ targets,  // (N, S)
                 const int*   __restrict__ input_lens,
                 const int*   __restrict__ target_lens,
                 float*       __restrict__ out)
{
    extern __shared__ unsigned char smem_raw[];
    float* rowbuf  = (float*)(smem_raw + OFF_ROWS);
    float* shAlpha = (float*)(smem_raw + OFF_ALPHA);
    volatile int* rowtag = (volatile int*)(smem_raw + OFF_RTAG);
    volatile int* prog   = (volatile int*)(smem_raw + OFF_PROG);
    volatile unsigned long long* halo =
        (volatile unsigned long long*)(smem_raw + OFF_HALO); // [NWC][HR][2]

    const int n    = blockIdx.x;
    const int tid  = threadIdx.x;
    const int w    = tid >> 5;
    const int lane = tid & 31;
    const size_t NC = (size_t)NN * CC;
    const float* __restrict__ base = lp + (size_t)n * CC;

    // ---- init control state ----
    if (tid < RING) rowtag[tid] = 0;           // < 1 => "not ready"
    if (tid < 16)   prog[tid]   = 0;
    if (tid < NWC * HR * 2) halo[tid] = 0xFFFFFFFF00000000ull; // tag = -1
    __syncthreads();

    // ================= producer warp =================
    if (w == NWC) {
        for (int r = 1; r < TT; ++r) {
            if (r >= RING) { while (prog[NWC - 1] < r - (RING - 1)) {} }
            const float* g = base + (size_t)r * NC + lane * 4;
            float* d = rowbuf + (size_t)(r & (RING - 1)) * CC + lane * 4;
#pragma unroll
            for (int i = 0; i < 4; ++i) cp_async16(d + i * 128, g + i * 128);
            cp_commit();
            if (r >= 4) { cp_wait<3>(); if (lane == 0) rowtag[(r - 3) & (RING - 1)] = r - 3; }
        }
        cp_wait<0>();
        if (lane == 0) {
            rowtag[(TT - 3) & (RING - 1)] = TT - 3;
            rowtag[(TT - 2) & (RING - 1)] = TT - 2;
            rowtag[(TT - 1) & (RING - 1)] = TT - 1;
        }
        return;
    }

    // ================= compute warps =================
    const int  s      = tid;          // one state per thread
    const bool active = (s < LL);
    const int  tl = target_lens[n];
    const int  il = input_lens[n];

    int  myExt = 0;
    bool allow = false;
    if (active && (s & 1)) {
        myExt = targets[n * SS + (s >> 1)];
        if (s >= 3) allow = (myExt != targets[n * SS + (s >> 1) - 1]);
    }

    // alpha_0 (log2 domain)
    float alphaReg = NEG2;
    if (s == 0) alphaReg = base[0] * LOG2E;
    else if (s == 1 && tl >= 1) alphaReg = base[myExt] * LOG2E;

    // publish halo for t = 0 (tag 0)
    if (w < NWC - 1 && lane >= 30)
        halo[(w * HR + 0) * 2 + (lane & 1)] =
            ((unsigned long long)0u << 32) | (unsigned long long)__float_as_uint(alphaReg);

    for (int t = 1; t < TT; ++t) {
        // ---- wait for emit row t ----
        const int rs = t & (RING - 1);
        while (rowtag[rs] < t) {}
        const float emit = rowbuf[(size_t)rs * CC + myExt] * LOG2E;

        // ---- halo from previous warp (states 32w-2, 32w-1 at time t-1) ----
        float h1 = NEG2, h2 = NEG2;
        if (w > 0) {
            const int hs = ((w - 1) * HR + ((t - 1) & (HR - 1))) * 2;
            unsigned long long v0, v1;
            do { v0 = halo[hs];     } while ((int)(v0 >> 32) < t - 1);
            do { v1 = halo[hs + 1]; } while ((int)(v1 >> 32) < t - 1);
            h2 = __uint_as_float((unsigned)v0);   // state 32w-2
            h1 = __uint_as_float((unsigned)v1);   // state 32w-1
        }

        const float aOld = alphaReg;
        const float up1 = __shfl_up_sync(0xffffffffu, aOld, 1);
        const float up2 = __shfl_up_sync(0xffffffffu, aOld, 2);
        float a1 = (lane == 0) ? h1 : up1;
        float a2 = (lane == 0) ? h2 : ((lane == 1) ? h1 : up2);
        a2 = allow ? a2 : NEG2;

        const float hi  = fmaxf(aOld, a1);
        const float lo  = fminf(aOld, a1);
        const float m   = fmaxf(hi, a2);
        const float mid = fminf(hi, a2);
        const float sum = 1.0f + ex2f(lo - m) + ex2f(mid - m);
        const float nv  = m + lg2f(sum) + emit;
        alphaReg = (t < il) ? nv : aOld;

        // ---- publish halo for time t (with ring back-pressure) ----
        if (w < NWC - 1) {
            if (t >= HR) { while (prog[w + 1] < t - (HR - 1)) {} }
            if (lane >= 30)
                halo[(w * HR + (t & (HR - 1))) * 2 + (lane & 1)] =
                    ((unsigned long long)(unsigned)t << 32) |
                    (unsigned long long)__float_as_uint(alphaReg);
        }
        if (lane == 0) prog[w] = t;
    }

    // ---- collect final alpha, compute per-example loss, fused reduce ----
    if (active) shAlpha[s] = alphaReg;
    asm volatile("bar.sync 1, %0;" :: "r"(NWC * 32) : "memory");

    if (tid == 0) {
        const int i_last = 2 * tl;
        const float al  = shAlpha[i_last];
        const float apv = (tl > 0) ? shAlpha[i_last - 1] : NEG2;
        const float mm  = fmaxf(al, apv);
        const float ll  = fminf(al, apv);
        float loss = -LN2 * (mm + lg2f(1.0f + ex2f(ll - mm)));
        if (!(loss < 1e29f)) loss = 0.0f;                 // zero_infinity (+NaN kill)
        const float norm = sqrtf(fmaxf((float)tl, 1.0f)); // ALPHA = 0.5
        ((volatile float*)g_per_ex)[n] = loss / norm;
        __threadfence();
        unsigned int old = atomicAdd(&g_count, 1u);
        if ((old % NN) == (NN - 1)) {                     // last CTA reduces
            __threadfence();
            float sacc = 0.0f;
#pragma unroll
            for (int i = 0; i < NN; ++i) sacc += ((volatile float*)g_per_ex)[i];
            out[0] = sacc / (float)NN;
        }
    }
}

extern "C" void kernel_launch(void* const* d_in, const int* in_sizes, int n_in,
                              void* d_out, int out_size)
{
    const float* log_probs   = (const float*)d_in[0];
    const int*   targets     = (const int*)d_in[1];
    const int*   input_lens  = (const int*)d_in[2];
    const int*   target_lens = (const int*)d_in[3];
    float* out = (float*)d_out;

    cudaFuncSetAttribute(ctc_fused_kernel,
                         cudaFuncAttributeMaxDynamicSharedMemorySize, SMEM_BYTES);
    ctc_fused_kernel<<<NN, THREADS, SMEM_BYTES>>>(log_probs, targets,
                                                  input_lens, target_lens, out);
}

// round 4
// speedup vs baseline: 3.6126x; 3.6126x over previous
#include <cuda_runtime.h>
#include <math.h>

// Problem constants (fixed by dataset)
#define TT 1600
#define NN 32
#define CC 512
#define SS 200
#define LL 401
#define RINGR 16                  // row ring slots (power of 2)
#define KSTEP 3                   // trellis steps per barrier period
#define STRIDE 26                 // 32 - 2*KSTEP  (valid states per warp)
#define THREADS 512               // 16 warps
#define NPER 533                  // (TT-1)/KSTEP, exact: 533*3 = 1599
#define LOG2E 1.4426950408889634f
#define LN2   0.6931471805599453f
#define NEG2  (-1.0e30f * 1.4426950408889634f)

__device__ float g_per_ex[NN];
__device__ unsigned int g_count;

__device__ __forceinline__ float ex2f(float x) {
    float y; asm("ex2.approx.ftz.f32 %0, %1;" : "=f"(y) : "f"(x)); return y;
}
__device__ __forceinline__ float lg2f(float x) {
    float y; asm("lg2.approx.ftz.f32 %0, %1;" : "=f"(y) : "f"(x)); return y;
}
__device__ __forceinline__ void cp_async4(void* smem_dst, const void* gmem_src) {
    unsigned s = (unsigned)__cvta_generic_to_shared(smem_dst);
    asm volatile("cp.async.ca.shared.global [%0], [%1], 4;" :: "r"(s), "l"(gmem_src));
}
__device__ __forceinline__ void cp_commit() { asm volatile("cp.async.commit_group;"); }
template<int N>
__device__ __forceinline__ void cp_wait() { asm volatile("cp.async.wait_group %0;" :: "n"(N)); }

__global__ void __launch_bounds__(THREADS, 1)
ctc_kernel(const float* __restrict__ lp,       // (T, N, C)
           const int*   __restrict__ targets,  // (N, S)
           const int*   __restrict__ input_lens,
           const int*   __restrict__ target_lens,
           float*       __restrict__ out)
{
    __shared__ float rowbuf[RINGR][CC];   // 32 KB emit-row ring
    __shared__ float shA[2][LL];          // alpha halo exchange, ping-pong

    const int n    = blockIdx.x;
    const int tid  = threadIdx.x;
    const int w    = tid >> 5;
    const int lane = tid & 31;
    // warp w owns states [26w, 26w+25] on lanes 6..31; lanes 0..5 are halo
    const int  s     = STRIDE * w + lane - 6;
    const bool sval  = (s >= 0) && (s < LL);
    const bool owner = sval && (lane >= 6);

    const size_t NC = (size_t)NN * CC;
    const float* __restrict__ base = lp + (size_t)n * CC;
    const int tl = target_lens[n];
    const int il = input_lens[n];

    // ---- per-state invariants ----
    int  myExt = 0;
    bool allow = false;
    if (sval && (s & 1)) {
        myExt = targets[n * SS + (s >> 1)];
        if (s >= 3) allow = (myExt != targets[n * SS + (s >> 1) - 1]);
    }

    // ---- alpha_0 (log2 domain) ----
    float alphaReg = NEG2;
    if (s == 0) alphaReg = base[0] * LOG2E;
    else if (s == 1 && tl >= 1) alphaReg = base[myExt] * LOG2E;
    if (owner) shA[1][s] = alphaReg;      // "period -1" buffer = 1

    // ---- cp.async prologue: rows for periods 0..2 (rows 1..9) ----
#pragma unroll
    for (int q = 0; q < 3; ++q) {
#pragma unroll
        for (int k = 1; k <= KSTEP; ++k) {
            const int r = 3 * q + k;
            cp_async4(&rowbuf[r & (RINGR - 1)][tid], base + (size_t)r * NC + tid);
        }
        cp_commit();
    }

    // ---- main loop: 3 trellis steps per barrier period ----
    for (int p = 0; p < NPER; ++p) {
        cp_wait<2>();            // this period's 3 rows have landed
        __syncthreads();         // rows + previous period's shA visible

        // halo refresh for lanes 0..5 (reads buffer written last period)
        if (lane < 6 && sval) alphaReg = shA[(p & 1) ^ 1][s];

        const int t0 = 3 * p;
        // issue all 3 emit gathers up front (latency overlaps step 1)
        const float e1 = rowbuf[(t0 + 1) & (RINGR - 1)][myExt] * LOG2E;
        const float e2 = rowbuf[(t0 + 2) & (RINGR - 1)][myExt] * LOG2E;
        const float e3 = rowbuf[(t0 + 3) & (RINGR - 1)][myExt] * LOG2E;

#pragma unroll
        for (int k = 1; k <= KSTEP; ++k) {
            const int   t    = t0 + k;
            const float emit = (k == 1) ? e1 : (k == 2) ? e2 : e3;
            const float a0 = alphaReg;
            float a1 = __shfl_up_sync(0xffffffffu, a0, 1);
            float a2 = __shfl_up_sync(0xffffffffu, a0, 2);
            a2 = allow ? a2 : NEG2;
            const float hi  = fmaxf(a0, a1);
            const float lo  = fminf(a0, a1);
            const float m   = fmaxf(hi, a2);
            const float mid = fminf(hi, a2);
            const float nv  = m + lg2f(1.0f + ex2f(lo - m) + ex2f(mid - m)) + emit;
            const float res = (t < il) ? nv : a0;
            alphaReg = sval ? res : NEG2;   // clamp out-of-range states (keeps s<0 == NEG)
        }

        // prefetch rows for period p+3 (slots never collide with live reads)
        {
            const int r0 = 3 * (p + 3);
#pragma unroll
            for (int k = 1; k <= KSTEP; ++k) {
                const int r = r0 + k;
                if (r < TT)
                    cp_async4(&rowbuf[r & (RINGR - 1)][tid], base + (size_t)r * NC + tid);
            }
            cp_commit();   // commit even if empty: keeps group accounting aligned
        }

        // publish this period's alpha for next period's halo
        if (owner) shA[p & 1][s] = alphaReg;
    }

    __syncthreads();

    // ---- readout + fused mean reduction ----
    if (tid == 0) {
        const float* a = shA[(NPER - 1) & 1];       // buffer 0
        const int i_last = 2 * tl;
        const float al  = a[i_last];
        const float apv = (tl > 0) ? a[i_last - 1] : NEG2;
        const float mm  = fmaxf(al, apv);
        const float lo  = fminf(al, apv);
        float loss = -LN2 * (mm + lg2f(1.0f + ex2f(lo - mm)));
        if (!(loss < 1e29f)) loss = 0.0f;            // zero_infinity (+NaN kill)
        const float norm = sqrtf(fmaxf((float)tl, 1.0f));  // ALPHA = 0.5
        ((volatile float*)g_per_ex)[n] = loss / norm;
        __threadfence();
        const unsigned int old = atomicAdd(&g_count, 1u);
        if ((old % NN) == (NN - 1)) {                // last CTA of this replay reduces
            __threadfence();
            float acc = 0.0f;
#pragma unroll
            for (int i = 0; i < NN; ++i) acc += ((volatile float*)g_per_ex)[i];
            out[0] = acc / (float)NN;
        }
    }
}

extern "C" void kernel_launch(void* const* d_in, const int* in_sizes, int n_in,
                              void* d_out, int out_size)
{
    const float* log_probs   = (const float*)d_in[0];
    const int*   targets     = (const int*)d_in[1];
    const int*   input_lens  = (const int*)d_in[2];
    const int*   target_lens = (const int*)d_in[3];
    float* out = (float*)d_out;

    ctc_kernel<<<NN, THREADS>>>(log_probs, targets, input_lens, target_lens, out);
}